// round 11
// baseline (speedup 1.0000x reference)
#include <cuda_runtime.h>
#include <cuda_fp16.h>
#include <stdint.h>
#include <math.h>

#define BATCH 8
#define LSEQ  4096
#define DIN   256
#define M_TOT 32768
#define N_TOT 1536
#define K_TOT 768
#define LP    4098   // padded rows per batch (one zero row each side)

// ---------------- scratch (static device globals) ----------------
__device__ __align__(16) __half g_xh[BATCH * LP * DIN];
__device__ __align__(16) __half g_wh[N_TOT * K_TOT];
__device__ __align__(16) __half g_gates[(size_t)M_TOT * N_TOT];   // fp16 activated gates (~100MB)
// fused-scan scratch: 16 chains (dir,b) x 128 chunks x 256 channels
#define NCH 128
#define CHLEN 32
__device__ float g_aggF[16 * NCH * 256];
__device__ float g_aggC[16 * NCH * 256];
__device__ int   g_flag[16 * NCH];

// ---------------- PTX helpers (arch-agnostic, compute_80-era) ----------------
__device__ __forceinline__ uint32_t smem_u32(const void* p) {
    uint32_t a;
    asm("{ .reg .u64 t; cvta.to.shared.u64 t, %1; cvt.u32.u64 %0, t; }" : "=r"(a) : "l"(p));
    return a;
}
__device__ __forceinline__ void cp16(uint32_t dst, const void* src) {
    asm volatile("cp.async.cg.shared.global [%0], [%1], 16;" :: "r"(dst), "l"(src));
}
__device__ __forceinline__ void cp_commit() {
    asm volatile("cp.async.commit_group;" ::: "memory");
}
template<int N> __device__ __forceinline__ void cp_wait() {
    asm volatile("cp.async.wait_group %0;" :: "n"(N) : "memory");
}
__device__ __forceinline__ void ldsm4(uint32_t* r, uint32_t addr) {
    asm volatile("ldmatrix.sync.aligned.m8n8.x4.shared.b16 {%0,%1,%2,%3}, [%4];"
                 : "=r"(r[0]), "=r"(r[1]), "=r"(r[2]), "=r"(r[3]) : "r"(addr));
}
__device__ __forceinline__ void mma_f16(float* d, const uint32_t* a, uint32_t b0, uint32_t b1) {
    asm volatile("mma.sync.aligned.m16n8k16.row.col.f32.f16.f16.f32 "
                 "{%0,%1,%2,%3}, {%4,%5,%6,%7}, {%8,%9}, {%0,%1,%2,%3};"
                 : "+f"(d[0]), "+f"(d[1]), "+f"(d[2]), "+f"(d[3])
                 : "r"(a[0]), "r"(a[1]), "r"(a[2]), "r"(a[3]), "r"(b0), "r"(b1));
}
// streaming load of a gate half (last-use, evict-first)
__device__ __forceinline__ __half ldcs_h(const __half* p) {
    unsigned short u = __ldcs((const unsigned short*)p);
    return __ushort_as_half(u);
}
__device__ __forceinline__ float ldcs_half(const __half* p) {
    return __half2float(ldcs_h(p));
}

// ---------------------------------------------------------------------------
// Kernel 1: merged prep — x pad/convert, weight relayout, scan-flag reset
// ---------------------------------------------------------------------------
__global__ void prep_all(const float* __restrict__ x,
                         const float* __restrict__ Wf,
                         const float* __restrict__ Wb) {
    int idx = blockIdx.x * blockDim.x + threadIdx.x;

    if (idx < 16 * NCH) g_flag[idx] = 0;

    // weight task: [c][kk=tap*256+i] fp16
    if (idx < N_TOT * K_TOT) {
        int c = idx / K_TOT;
        int kk = idx - c * K_TOT;
        int tap = kk >> 8;
        int i = kk & 255;
        float v = (c < 768) ? Wf[c * 768 + i * 3 + tap] : Wb[(c - 768) * 768 + i * 3 + tap];
        g_wh[idx] = __float2half_rn(v);
    }

    // x task: 8 elements per thread, rows b*(L+2) + (l+1)
    const int TOT8 = BATCH * LP * DIN / 8;
    if (idx < TOT8) {
        int e0 = idx * 8;
        int b = e0 / (LP * DIN);
        int rem = e0 - b * LP * DIN;
        int r = rem / DIN;
        int i = rem - r * DIN;
        int l = r - 1;
        float v[8];
        if (l >= 0 && l < LSEQ) {
            const float4* src = (const float4*)(x + ((size_t)(b * LSEQ + l)) * DIN + i);
            float4 a = src[0], c = src[1];
            v[0]=a.x; v[1]=a.y; v[2]=a.z; v[3]=a.w; v[4]=c.x; v[5]=c.y; v[6]=c.z; v[7]=c.w;
        } else {
#pragma unroll
            for (int j = 0; j < 8; j++) v[j] = 0.f;
        }
        __half h[8];
#pragma unroll
        for (int j = 0; j < 8; j++) h[j] = __float2half_rn(v[j]);
        *(uint4*)(g_xh + e0) = *(uint4*)h;
    }
}

// ---------------------------------------------------------------------------
// Kernel 2: persistent fp16 HMMA GEMM + bias + activation -> g_gates (fp16)
// BM=128, BN=128, BK=32, 256 threads, warp tile 32x64, 4-stage cp.async
// grid = 296 (one wave, 2 CTAs/SM), each CTA loops over tiles
// ---------------------------------------------------------------------------
#define STAGES 4
#define STAGE_BYTES 16384     // A: 128*64B = 8192, B: 128*64B = 8192
#define GEMM_SMEM (STAGES * STAGE_BYTES)
#define NIT 24
#define NTILES 3072           // 12 n-blocks x 256 m-blocks
#define GEMM_GRID 296

__device__ __forceinline__ float actv(float v, int ctype) {
    if (ctype == 2) {
        float t = __expf(-2.f * fabsf(v));
        float r = (1.f - t) / (1.f + t);
        return copysignf(r, v);
    }
    return 1.f / (1.f + __expf(-v));
}

__device__ __forceinline__ void gemm_issue(uint32_t smemU, int stage, int kchunk,
                                           int rbase, int n0, int tid) {
    int kc = kchunk * 32;
    int tap = kc >> 8;
    int i0 = kc & 255;
    uint32_t abase = smemU + stage * STAGE_BYTES;
    uint32_t bbase = abase + 8192;
#pragma unroll
    for (int q = 0; q < 2; q++) {
        int idx = tid + q * 256;
        int row = idx >> 2, c16 = idx & 3;
        int chunk = c16 ^ (row & 3) ^ ((row >> 2) & 1);
        cp16(abase + row * 64 + chunk * 16,
             g_xh + (size_t)(rbase + tap + row) * 256 + i0 + c16 * 8);
    }
#pragma unroll
    for (int q = 0; q < 2; q++) {
        int idx = tid + q * 256;
        int row = idx >> 2, c16 = idx & 3;
        int chunk = c16 ^ (row & 3) ^ ((row >> 2) & 1);
        cp16(bbase + row * 64 + chunk * 16,
             g_wh + (size_t)(n0 + row) * 768 + kc + c16 * 8);
    }
}

__global__ __launch_bounds__(256, 2)
void gemm_hmma(const float* __restrict__ bfv, const float* __restrict__ bbv) {
    extern __shared__ char smem[];
    uint32_t smemU = smem_u32(smem);
    const int tid = threadIdx.x;
    const int lane = tid & 31;
    const int w = tid >> 5;
    const int wm = w >> 1;          // 0..3  (32-row slices)
    const int wn = w & 1;           // 0..1  (64-col slices)

    // per-thread ldmatrix read offsets (tile-independent)
    const int lr = lane & 7;
    const int grp = lane >> 3;
    const int arow = wm * 32 + (grp & 1) * 8 + lr;
    const int achk = (grp >> 1) ^ (arow & 3) ^ ((arow >> 2) & 1);
    const uint32_t aoff0 = (uint32_t)(arow * 64 + achk * 16);
    const int brow = wn * 64 + (grp >> 1) * 8 + lr;
    const int bchk = (grp & 1) ^ (brow & 3) ^ ((brow >> 2) & 1);
    const uint32_t boff0 = (uint32_t)(8192 + brow * 64 + bchk * 16);

#pragma unroll 1
    for (int t = blockIdx.x; t < NTILES; t += GEMM_GRID) {
        const int n0 = (t % 12) * 128;
        const int m0 = (t / 12) * 128;
        const int batch = m0 >> 12;
        const int l0 = m0 & 4095;
        const int rbase = batch * LP + l0;

        __syncthreads();   // previous tile's compute fully done before smem reuse

        float acc[2][8][4];
#pragma unroll
        for (int mt = 0; mt < 2; mt++)
#pragma unroll
            for (int nt = 0; nt < 8; nt++)
#pragma unroll
                for (int r = 0; r < 4; r++) acc[mt][nt][r] = 0.f;

        // prologue: fill 3 stages
#pragma unroll
        for (int s = 0; s < STAGES - 1; s++) {
            gemm_issue(smemU, s, s, rbase, n0, tid);
            cp_commit();
        }

#pragma unroll 1
        for (int j = 0; j < NIT; j++) {
            cp_wait<STAGES - 2>();
            __syncthreads();
            if (j + STAGES - 1 < NIT)
                gemm_issue(smemU, (j + STAGES - 1) & (STAGES - 1), j + STAGES - 1, rbase, n0, tid);
            cp_commit();

            uint32_t stbase = smemU + (j & (STAGES - 1)) * STAGE_BYTES;
#pragma unroll
            for (int ks = 0; ks < 2; ks++) {
                uint32_t a[2][4], b[4][4];
#pragma unroll
                for (int mt = 0; mt < 2; mt++)
                    ldsm4(a[mt], (stbase + aoff0 + mt * 1024) ^ (ks * 32));
#pragma unroll
                for (int np = 0; np < 4; np++)
                    ldsm4(b[np], (stbase + boff0 + np * 1024) ^ (ks * 32));
#pragma unroll
                for (int mt = 0; mt < 2; mt++)
#pragma unroll
                    for (int nt = 0; nt < 8; nt++)
                        mma_f16(acc[mt][nt], a[mt], b[nt >> 1][(nt & 1) * 2], b[nt >> 1][(nt & 1) * 2 + 1]);
            }
        }

        // epilogue: bias + activation -> fp16 gates
        const int ctype = (n0 >> 8) % 3;
        const float* bsrc = (n0 < 768) ? bfv : bbv;
        const int cofs = (n0 < 768) ? n0 : (n0 - 768);

#pragma unroll
        for (int mt = 0; mt < 2; mt++) {
            int mrow = m0 + wm * 32 + mt * 16 + (lane >> 2);
            __half* d0 = g_gates + (size_t)mrow * N_TOT + n0;
            __half* d1 = d0 + (size_t)8 * N_TOT;
#pragma unroll
            for (int nt = 0; nt < 8; nt++) {
                int cc = wn * 64 + nt * 8 + (lane & 3) * 2;
                float bb0 = bsrc[cofs + cc];
                float bb1 = bsrc[cofs + cc + 1];
                __half2 v0, v1;
                v0.x = __float2half_rn(actv(acc[mt][nt][0] + bb0, ctype));
                v0.y = __float2half_rn(actv(acc[mt][nt][1] + bb1, ctype));
                v1.x = __float2half_rn(actv(acc[mt][nt][2] + bb0, ctype));
                v1.y = __float2half_rn(actv(acc[mt][nt][3] + bb1, ctype));
                *(__half2*)(d0 + cc) = v0;
                *(__half2*)(d1 + cc) = v1;
            }
        }
    }
}

// ---------------------------------------------------------------------------
// Kernel 3: single-read fused scan. CHLEN=32 so each thread's f,z chunk gates
// stay in registers between pass 1 (aggregate) and pass 2 (output).
// Deterministic all-aggregate lookback (fold predecessors ascending).
// bid = chain*NCH + pos (pos ascending => waits target lower bids only).
// ---------------------------------------------------------------------------
__global__ __launch_bounds__(256)
void scan_fused(float* __restrict__ out) {
    const int bid = blockIdx.x;
    const int chain = bid >> 7;          // 0..15
    const int pos = bid & (NCH - 1);     // 0..127
    const int dir = chain >> 3;
    const int b = chain & 7;
    const int ch = (dir == 0) ? pos : (NCH - 1 - pos);   // chunk index in l-space
    const int d = threadIdx.x;
    const int slot = chain * NCH + pos;
    const size_t OUT_HL = (size_t)BATCH * LSEQ * 512;

    const int row0 = (dir == 0) ? (b * LSEQ + ch * CHLEN)
                                : (b * LSEQ + ch * CHLEN + CHLEN - 1);
    const int rstep = (dir == 0) ? N_TOT : -N_TOT;
    const int goff = (dir == 0) ? d : (768 + d);

    // ---- pass 1: read f,z once (streaming), stash in regs, aggregate ----
    __half2 hz[CHLEN];                 // packed (f, z) per step
    float F = 1.f, C = 0.f;
    {
        const __half* gp = g_gates + (size_t)row0 * N_TOT + goff;
#pragma unroll
        for (int s = 0; s < CHLEN; s++) {
            __half fh = ldcs_h(gp);
            __half zh = ldcs_h(gp + 512);
            hz[s] = __halves2half2(fh, zh);
            float f = __half2float(fh), z = __half2float(zh);
            C = f * C + (1.f - f) * z;
            F *= f;
            gp += rstep;
        }
    }
    g_aggF[slot * 256 + d] = F;
    g_aggC[slot * 256 + d] = C;
    __syncthreads();
    __threadfence();
    if (d == 0) atomicExch(&g_flag[slot], 1);

    // ---- lookback: wait for all predecessor aggregates, fold ascending ----
    float c = 0.f;
    if (pos > 0) {
        if (d < pos) {
            while (atomicAdd(&g_flag[chain * NCH + d], 0) == 0) { __nanosleep(64); }
        }
        __syncthreads();
        __threadfence();
        const float* aF = g_aggF + (size_t)chain * NCH * 256 + d;
        const float* aC = g_aggC + (size_t)chain * NCH * 256 + d;
#pragma unroll 1
        for (int j = 0; j < pos; j++) {
            float Fj = aF[j * 256];
            float Cj = aC[j * 256];
            c = Fj * c + Cj;
        }
    }

    // ---- pass 2: recurrence from registers; o streamed; outputs __stcs ----
    const __half* gpo = g_gates + (size_t)row0 * N_TOT + goff + 256;
    float* op = out + (size_t)row0 * 512 + (dir ? 256 : 0) + d;
    const int ostep = (dir == 0) ? 512 : -512;

    float h = 0.f;
    float h_first = 0.f, c_first = 0.f;
#pragma unroll
    for (int s = 0; s < CHLEN; s++) {
        float2 fz = __half22float2(hz[s]);
        float o = ldcs_half(gpo);
        c = fz.x * c + (1.f - fz.x) * fz.y;
        h = c * o;
        __stcs(op, h);
        if (s == 0) { h_first = h; c_first = c; }
        gpo += rstep;
        op += ostep;
    }

    if (dir == 0) {
        if (pos == NCH - 1) {   // last forward chunk ends at l = L-1
            __stcs(out + OUT_HL + b * 512 + d, h);
            __stcs(out + OUT_HL + 4096 + b * 512 + d, c);
        }
    } else {
        if (pos == 0) {         // first backward chunk processes l = L-1 first
            __stcs(out + OUT_HL + b * 512 + 256 + d, h_first);
            __stcs(out + OUT_HL + 4096 + b * 512 + 256 + d, c_first);
        }
    }
}

// ---------------------------------------------------------------------------
extern "C" void kernel_launch(void* const* d_in, const int* in_sizes, int n_in,
                              void* d_out, int out_size) {
    const float* x  = (const float*)d_in[0];
    const float* Wf = (const float*)d_in[2];
    const float* bf = (const float*)d_in[3];
    const float* Wb = (const float*)d_in[4];
    const float* bb = (const float*)d_in[5];
    float* out = (float*)d_out;

    cudaFuncSetAttribute(gemm_hmma, cudaFuncAttributeMaxDynamicSharedMemorySize, GEMM_SMEM);

    {
        int totw = N_TOT * K_TOT;                      // largest task
        prep_all<<<(totw + 255) / 256, 256>>>(x, Wf, Wb);
    }
    gemm_hmma<<<GEMM_GRID, 256, GEMM_SMEM>>>(bf, bb);
    scan_fused<<<16 * NCH, 256>>>(out);
}

// round 12
// speedup vs baseline: 1.5398x; 1.5398x over previous
#include <cuda_runtime.h>
#include <cuda_fp16.h>
#include <stdint.h>
#include <math.h>

#define BATCH 8
#define LSEQ  4096
#define DIN   256
#define M_TOT 32768
#define N_TOT 1536
#define K_TOT 768
#define LP    4098   // padded rows per batch (one zero row each side)

// ---------------- scratch (static device globals) ----------------
__device__ __align__(16) __half g_xh[BATCH * LP * DIN];
__device__ __align__(16) __half g_wh[N_TOT * K_TOT];
__device__ __align__(16) __half g_gates[(size_t)M_TOT * N_TOT];   // fp16 activated gates (~100MB)
// fused-scan scratch: 16 chains (dir,b) x 64 chunks x 256 channels
#define NCH 64
#define CHLEN 64
#define STASH 16
__device__ float g_aggF[16 * NCH * 256];
__device__ float g_aggC[16 * NCH * 256];
__device__ int   g_flag[16 * NCH];

// ---------------- PTX helpers (arch-agnostic, compute_80-era) ----------------
__device__ __forceinline__ uint32_t smem_u32(const void* p) {
    uint32_t a;
    asm("{ .reg .u64 t; cvta.to.shared.u64 t, %1; cvt.u32.u64 %0, t; }" : "=r"(a) : "l"(p));
    return a;
}
__device__ __forceinline__ void cp16(uint32_t dst, const void* src) {
    asm volatile("cp.async.cg.shared.global [%0], [%1], 16;" :: "r"(dst), "l"(src));
}
__device__ __forceinline__ void cp_commit() {
    asm volatile("cp.async.commit_group;" ::: "memory");
}
template<int N> __device__ __forceinline__ void cp_wait() {
    asm volatile("cp.async.wait_group %0;" :: "n"(N) : "memory");
}
__device__ __forceinline__ void ldsm4(uint32_t* r, uint32_t addr) {
    asm volatile("ldmatrix.sync.aligned.m8n8.x4.shared.b16 {%0,%1,%2,%3}, [%4];"
                 : "=r"(r[0]), "=r"(r[1]), "=r"(r[2]), "=r"(r[3]) : "r"(addr));
}
__device__ __forceinline__ void mma_f16(float* d, const uint32_t* a, uint32_t b0, uint32_t b1) {
    asm volatile("mma.sync.aligned.m16n8k16.row.col.f32.f16.f16.f32 "
                 "{%0,%1,%2,%3}, {%4,%5,%6,%7}, {%8,%9}, {%0,%1,%2,%3};"
                 : "+f"(d[0]), "+f"(d[1]), "+f"(d[2]), "+f"(d[3])
                 : "r"(a[0]), "r"(a[1]), "r"(a[2]), "r"(a[3]), "r"(b0), "r"(b1));
}
// streaming load of a gate half (last-use, evict-first)
__device__ __forceinline__ __half ldcs_h(const __half* p) {
    unsigned short u = __ldcs((const unsigned short*)p);
    return __ushort_as_half(u);
}
__device__ __forceinline__ float ldcs_half(const __half* p) {
    return __half2float(ldcs_h(p));
}

// ---------------------------------------------------------------------------
// Kernel 1: merged prep — x pad/convert, weight relayout, scan-flag reset
// ---------------------------------------------------------------------------
__global__ void prep_all(const float* __restrict__ x,
                         const float* __restrict__ Wf,
                         const float* __restrict__ Wb) {
    int idx = blockIdx.x * blockDim.x + threadIdx.x;

    if (idx < 16 * NCH) g_flag[idx] = 0;

    // weight task: [c][kk=tap*256+i] fp16
    if (idx < N_TOT * K_TOT) {
        int c = idx / K_TOT;
        int kk = idx - c * K_TOT;
        int tap = kk >> 8;
        int i = kk & 255;
        float v = (c < 768) ? Wf[c * 768 + i * 3 + tap] : Wb[(c - 768) * 768 + i * 3 + tap];
        g_wh[idx] = __float2half_rn(v);
    }

    // x task: 8 elements per thread, rows b*(L+2) + (l+1)
    const int TOT8 = BATCH * LP * DIN / 8;
    if (idx < TOT8) {
        int e0 = idx * 8;
        int b = e0 / (LP * DIN);
        int rem = e0 - b * LP * DIN;
        int r = rem / DIN;
        int i = rem - r * DIN;
        int l = r - 1;
        float v[8];
        if (l >= 0 && l < LSEQ) {
            const float4* src = (const float4*)(x + ((size_t)(b * LSEQ + l)) * DIN + i);
            float4 a = src[0], c = src[1];
            v[0]=a.x; v[1]=a.y; v[2]=a.z; v[3]=a.w; v[4]=c.x; v[5]=c.y; v[6]=c.z; v[7]=c.w;
        } else {
#pragma unroll
            for (int j = 0; j < 8; j++) v[j] = 0.f;
        }
        __half h[8];
#pragma unroll
        for (int j = 0; j < 8; j++) h[j] = __float2half_rn(v[j]);
        *(uint4*)(g_xh + e0) = *(uint4*)h;
    }
}

// ---------------------------------------------------------------------------
// Kernel 2: persistent fp16 HMMA GEMM + bias + activation -> g_gates (fp16)
// BM=128, BN=128, BK=32, 256 threads, warp tile 32x64, 4-stage cp.async
// grid = 296 (one wave, 2 CTAs/SM), each CTA loops over tiles
// ---------------------------------------------------------------------------
#define STAGES 4
#define STAGE_BYTES 16384     // A: 128*64B = 8192, B: 128*64B = 8192
#define GEMM_SMEM (STAGES * STAGE_BYTES)
#define NIT 24
#define NTILES 3072           // 12 n-blocks x 256 m-blocks
#define GEMM_GRID 296

__device__ __forceinline__ float actv(float v, int ctype) {
    if (ctype == 2) {
        float t = __expf(-2.f * fabsf(v));
        float r = (1.f - t) / (1.f + t);
        return copysignf(r, v);
    }
    return 1.f / (1.f + __expf(-v));
}

__device__ __forceinline__ void gemm_issue(uint32_t smemU, int stage, int kchunk,
                                           int rbase, int n0, int tid) {
    int kc = kchunk * 32;
    int tap = kc >> 8;
    int i0 = kc & 255;
    uint32_t abase = smemU + stage * STAGE_BYTES;
    uint32_t bbase = abase + 8192;
#pragma unroll
    for (int q = 0; q < 2; q++) {
        int idx = tid + q * 256;
        int row = idx >> 2, c16 = idx & 3;
        int chunk = c16 ^ (row & 3) ^ ((row >> 2) & 1);
        cp16(abase + row * 64 + chunk * 16,
             g_xh + (size_t)(rbase + tap + row) * 256 + i0 + c16 * 8);
    }
#pragma unroll
    for (int q = 0; q < 2; q++) {
        int idx = tid + q * 256;
        int row = idx >> 2, c16 = idx & 3;
        int chunk = c16 ^ (row & 3) ^ ((row >> 2) & 1);
        cp16(bbase + row * 64 + chunk * 16,
             g_wh + (size_t)(n0 + row) * 768 + kc + c16 * 8);
    }
}

__global__ __launch_bounds__(256, 2)
void gemm_hmma(const float* __restrict__ bfv, const float* __restrict__ bbv) {
    extern __shared__ char smem[];
    uint32_t smemU = smem_u32(smem);
    const int tid = threadIdx.x;
    const int lane = tid & 31;
    const int w = tid >> 5;
    const int wm = w >> 1;          // 0..3  (32-row slices)
    const int wn = w & 1;           // 0..1  (64-col slices)

    // per-thread ldmatrix read offsets (tile-independent)
    const int lr = lane & 7;
    const int grp = lane >> 3;
    const int arow = wm * 32 + (grp & 1) * 8 + lr;
    const int achk = (grp >> 1) ^ (arow & 3) ^ ((arow >> 2) & 1);
    const uint32_t aoff0 = (uint32_t)(arow * 64 + achk * 16);
    const int brow = wn * 64 + (grp >> 1) * 8 + lr;
    const int bchk = (grp & 1) ^ (brow & 3) ^ ((brow >> 2) & 1);
    const uint32_t boff0 = (uint32_t)(8192 + brow * 64 + bchk * 16);

#pragma unroll 1
    for (int t = blockIdx.x; t < NTILES; t += GEMM_GRID) {
        const int n0 = (t % 12) * 128;
        const int m0 = (t / 12) * 128;
        const int batch = m0 >> 12;
        const int l0 = m0 & 4095;
        const int rbase = batch * LP + l0;

        __syncthreads();   // previous tile's compute fully done before smem reuse

        float acc[2][8][4];
#pragma unroll
        for (int mt = 0; mt < 2; mt++)
#pragma unroll
            for (int nt = 0; nt < 8; nt++)
#pragma unroll
                for (int r = 0; r < 4; r++) acc[mt][nt][r] = 0.f;

        // prologue: fill 3 stages
#pragma unroll
        for (int s = 0; s < STAGES - 1; s++) {
            gemm_issue(smemU, s, s, rbase, n0, tid);
            cp_commit();
        }

#pragma unroll 1
        for (int j = 0; j < NIT; j++) {
            cp_wait<STAGES - 2>();
            __syncthreads();
            if (j + STAGES - 1 < NIT)
                gemm_issue(smemU, (j + STAGES - 1) & (STAGES - 1), j + STAGES - 1, rbase, n0, tid);
            cp_commit();

            uint32_t stbase = smemU + (j & (STAGES - 1)) * STAGE_BYTES;
#pragma unroll
            for (int ks = 0; ks < 2; ks++) {
                uint32_t a[2][4], b[4][4];
#pragma unroll
                for (int mt = 0; mt < 2; mt++)
                    ldsm4(a[mt], (stbase + aoff0 + mt * 1024) ^ (ks * 32));
#pragma unroll
                for (int np = 0; np < 4; np++)
                    ldsm4(b[np], (stbase + boff0 + np * 1024) ^ (ks * 32));
#pragma unroll
                for (int mt = 0; mt < 2; mt++)
#pragma unroll
                    for (int nt = 0; nt < 8; nt++)
                        mma_f16(acc[mt][nt], a[mt], b[nt >> 1][(nt & 1) * 2], b[nt >> 1][(nt & 1) * 2 + 1]);
            }
        }

        // epilogue: bias + activation -> fp16 gates
        const int ctype = (n0 >> 8) % 3;
        const float* bsrc = (n0 < 768) ? bfv : bbv;
        const int cofs = (n0 < 768) ? n0 : (n0 - 768);

#pragma unroll
        for (int mt = 0; mt < 2; mt++) {
            int mrow = m0 + wm * 32 + mt * 16 + (lane >> 2);
            __half* d0 = g_gates + (size_t)mrow * N_TOT + n0;
            __half* d1 = d0 + (size_t)8 * N_TOT;
#pragma unroll
            for (int nt = 0; nt < 8; nt++) {
                int cc = wn * 64 + nt * 8 + (lane & 3) * 2;
                float bb0 = bsrc[cofs + cc];
                float bb1 = bsrc[cofs + cc + 1];
                __half2 v0, v1;
                v0.x = __float2half_rn(actv(acc[mt][nt][0] + bb0, ctype));
                v0.y = __float2half_rn(actv(acc[mt][nt][1] + bb1, ctype));
                v1.x = __float2half_rn(actv(acc[mt][nt][2] + bb0, ctype));
                v1.y = __float2half_rn(actv(acc[mt][nt][3] + bb1, ctype));
                *(__half2*)(d0 + cc) = v0;
                *(__half2*)(d1 + cc) = v1;
            }
        }
    }
}

// ---------------------------------------------------------------------------
// Kernel 3: fused single-pass bidirectional fo-pool scan (R10 structure)
// + 16-step register stash (first STASH steps' f,z never re-read)
// + batched lookback fold (4 independent loads per chain step)
// Deterministic all-aggregate lookback (fold predecessors ascending).
// ---------------------------------------------------------------------------
__global__ __launch_bounds__(256)
void scan_fused(float* __restrict__ out) {
    const int bid = blockIdx.x;
    const int dir = bid >> 9;
    const int rem = bid & 511;
    const int b = rem >> 6;
    const int pos = rem & 63;
    const int ch = (dir == 0) ? pos : (NCH - 1 - pos);   // chunk index in l-space
    const int d = threadIdx.x;
    const int chain = dir * 8 + b;
    const int slot = chain * NCH + pos;
    const size_t OUT_HL = (size_t)BATCH * LSEQ * 512;

    const int row0 = (dir == 0) ? (b * LSEQ + ch * CHLEN)
                                : (b * LSEQ + ch * CHLEN + CHLEN - 1);
    const int rstep = (dir == 0) ? N_TOT : -N_TOT;
    const int goff = (dir == 0) ? d : (768 + d);

    // ---- pass 1: local aggregate; stash first STASH steps' f,z in regs ----
    __half2 hz[STASH];
    float F = 1.f, C = 0.f;
    {
        const __half* gp = g_gates + (size_t)row0 * N_TOT + goff;
#pragma unroll
        for (int s = 0; s < STASH; s++) {
            __half fh = ldcs_h(gp);          // last-use: replayed from regs
            __half zh = ldcs_h(gp + 512);
            hz[s] = __halves2half2(fh, zh);
            float f = __half2float(fh), z = __half2float(zh);
            C = f * C + (1.f - f) * z;
            F *= f;
            gp += rstep;
        }
#pragma unroll 4
        for (int s = STASH; s < CHLEN; s++) {
            float f = __half2float(gp[0]), z = __half2float(gp[512]);   // cached: pass-2 re-reads
            C = f * C + (1.f - f) * z;
            F *= f;
            gp += rstep;
        }
    }
    g_aggF[slot * 256 + d] = F;
    g_aggC[slot * 256 + d] = C;
    __syncthreads();
    __threadfence();
    if (d == 0) atomicExch(&g_flag[slot], 1);

    // ---- lookback: wait for all predecessors, fold ascending (batched) ----
    float c = 0.f;
    if (pos > 0) {
        if (d < pos) {
            while (atomicAdd(&g_flag[chain * NCH + d], 0) == 0) { __nanosleep(64); }
        }
        __syncthreads();
        __threadfence();
        const float* aF = g_aggF + (size_t)chain * NCH * 256 + d;
        const float* aC = g_aggC + (size_t)chain * NCH * 256 + d;
        int j = 0;
#pragma unroll 1
        for (; j + 4 <= pos; j += 4) {
            float F0 = aF[(j + 0) * 256], C0 = aC[(j + 0) * 256];
            float F1 = aF[(j + 1) * 256], C1 = aC[(j + 1) * 256];
            float F2 = aF[(j + 2) * 256], C2 = aC[(j + 2) * 256];
            float F3 = aF[(j + 3) * 256], C3 = aC[(j + 3) * 256];
            c = F0 * c + C0;
            c = F1 * c + C1;
            c = F2 * c + C2;
            c = F3 * c + C3;
        }
#pragma unroll 1
        for (; j < pos; j++) {
            c = aF[j * 256] * c + aC[j * 256];
        }
    }

    // ---- pass 2: stashed steps from regs; rest streamed; outputs __stcs ----
    const __half* gp = g_gates + (size_t)row0 * N_TOT + goff;
    float* op = out + (size_t)row0 * 512 + (dir ? 256 : 0) + d;
    const int ostep = (dir == 0) ? 512 : -512;

    float h = 0.f;
    float h_first = 0.f, c_first = 0.f;
#pragma unroll
    for (int s = 0; s < STASH; s++) {
        float2 fz = __half22float2(hz[s]);
        float o = ldcs_half(gp + 256);
        c = fz.x * c + (1.f - fz.x) * fz.y;
        h = c * o;
        __stcs(op, h);
        if (s == 0) { h_first = h; c_first = c; }
        gp += rstep;
        op += ostep;
    }
#pragma unroll 4
    for (int s = STASH; s < CHLEN; s++) {
        float f = ldcs_half(gp);
        float o = ldcs_half(gp + 256);
        float z = ldcs_half(gp + 512);
        c = f * c + (1.f - f) * z;
        h = c * o;
        __stcs(op, h);
        gp += rstep;
        op += ostep;
    }

    if (dir == 0) {
        if (pos == NCH - 1) {   // last forward chunk ends at l = L-1
            __stcs(out + OUT_HL + b * 512 + d, h);
            __stcs(out + OUT_HL + 4096 + b * 512 + d, c);
        }
    } else {
        if (pos == 0) {         // first backward chunk processes l = L-1 first
            __stcs(out + OUT_HL + b * 512 + 256 + d, h_first);
            __stcs(out + OUT_HL + 4096 + b * 512 + 256 + d, c_first);
        }
    }
}

// ---------------------------------------------------------------------------
extern "C" void kernel_launch(void* const* d_in, const int* in_sizes, int n_in,
                              void* d_out, int out_size) {
    const float* x  = (const float*)d_in[0];
    const float* Wf = (const float*)d_in[2];
    const float* bf = (const float*)d_in[3];
    const float* Wb = (const float*)d_in[4];
    const float* bb = (const float*)d_in[5];
    float* out = (float*)d_out;

    cudaFuncSetAttribute(gemm_hmma, cudaFuncAttributeMaxDynamicSharedMemorySize, GEMM_SMEM);

    {
        int totw = N_TOT * K_TOT;                      // largest task
        prep_all<<<(totw + 255) / 256, 256>>>(x, Wf, Wb);
    }
    gemm_hmma<<<GEMM_GRID, 256, GEMM_SMEM>>>(bf, bb);
    scan_fused<<<1024, 256>>>(out);
}

// round 13
// speedup vs baseline: 1.8518x; 1.2026x over previous
#include <cuda_runtime.h>
#include <cuda_fp16.h>
#include <stdint.h>
#include <math.h>

#define BATCH 8
#define LSEQ  4096
#define DIN   256
#define M_TOT 32768
#define N_TOT 1536
#define K_TOT 768
#define LP    4098   // padded rows per batch (one zero row each side)

// ---------------- scratch (static device globals) ----------------
__device__ __align__(16) __half g_xh[BATCH * LP * DIN];
__device__ __align__(16) __half g_wh[N_TOT * K_TOT];
__device__ __align__(16) __half g_gates[(size_t)M_TOT * N_TOT];   // fp16 activated gates (~100MB)
// fused-scan scratch: 16 chains (dir,b) x 64 chunks x 256 channels
#define NCH 64
#define CHLEN 64
__device__ float g_aggF[16 * NCH * 256];
__device__ float g_aggC[16 * NCH * 256];
__device__ int   g_flag[16 * NCH];

// ---------------- PTX helpers (arch-agnostic, compute_80-era) ----------------
__device__ __forceinline__ uint32_t smem_u32(const void* p) {
    uint32_t a;
    asm("{ .reg .u64 t; cvta.to.shared.u64 t, %1; cvt.u32.u64 %0, t; }" : "=r"(a) : "l"(p));
    return a;
}
__device__ __forceinline__ void cp16(uint32_t dst, const void* src) {
    asm volatile("cp.async.cg.shared.global [%0], [%1], 16;" :: "r"(dst), "l"(src));
}
__device__ __forceinline__ void cp_commit() {
    asm volatile("cp.async.commit_group;" ::: "memory");
}
template<int N> __device__ __forceinline__ void cp_wait() {
    asm volatile("cp.async.wait_group %0;" :: "n"(N) : "memory");
}
__device__ __forceinline__ void ldsm4(uint32_t* r, uint32_t addr) {
    asm volatile("ldmatrix.sync.aligned.m8n8.x4.shared.b16 {%0,%1,%2,%3}, [%4];"
                 : "=r"(r[0]), "=r"(r[1]), "=r"(r[2]), "=r"(r[3]) : "r"(addr));
}
__device__ __forceinline__ void mma_f16(float* d, const uint32_t* a, uint32_t b0, uint32_t b1) {
    asm volatile("mma.sync.aligned.m16n8k16.row.col.f32.f16.f16.f32 "
                 "{%0,%1,%2,%3}, {%4,%5,%6,%7}, {%8,%9}, {%0,%1,%2,%3};"
                 : "+f"(d[0]), "+f"(d[1]), "+f"(d[2]), "+f"(d[3])
                 : "r"(a[0]), "r"(a[1]), "r"(a[2]), "r"(a[3]), "r"(b0), "r"(b1));
}
// streaming load of a gate half (last-use, evict-first)
__device__ __forceinline__ float ldcs_half(const __half* p) {
    unsigned short u = __ldcs((const unsigned short*)p);
    return __half2float(__ushort_as_half(u));
}

// ---------------------------------------------------------------------------
// Kernel 1: merged prep — x pad/convert, weight relayout, scan-flag reset
// ---------------------------------------------------------------------------
__global__ void prep_all(const float* __restrict__ x,
                         const float* __restrict__ Wf,
                         const float* __restrict__ Wb) {
    int idx = blockIdx.x * blockDim.x + threadIdx.x;

    if (idx < 16 * NCH) g_flag[idx] = 0;

    // weight task: [c][kk=tap*256+i] fp16
    if (idx < N_TOT * K_TOT) {
        int c = idx / K_TOT;
        int kk = idx - c * K_TOT;
        int tap = kk >> 8;
        int i = kk & 255;
        float v = (c < 768) ? Wf[c * 768 + i * 3 + tap] : Wb[(c - 768) * 768 + i * 3 + tap];
        g_wh[idx] = __float2half_rn(v);
    }

    // x task: 8 elements per thread, rows b*(L+2) + (l+1)
    const int TOT8 = BATCH * LP * DIN / 8;
    if (idx < TOT8) {
        int e0 = idx * 8;
        int b = e0 / (LP * DIN);
        int rem = e0 - b * LP * DIN;
        int r = rem / DIN;
        int i = rem - r * DIN;
        int l = r - 1;
        float v[8];
        if (l >= 0 && l < LSEQ) {
            const float4* src = (const float4*)(x + ((size_t)(b * LSEQ + l)) * DIN + i);
            float4 a = src[0], c = src[1];
            v[0]=a.x; v[1]=a.y; v[2]=a.z; v[3]=a.w; v[4]=c.x; v[5]=c.y; v[6]=c.z; v[7]=c.w;
        } else {
#pragma unroll
            for (int j = 0; j < 8; j++) v[j] = 0.f;
        }
        __half h[8];
#pragma unroll
        for (int j = 0; j < 8; j++) h[j] = __float2half_rn(v[j]);
        *(uint4*)(g_xh + e0) = *(uint4*)h;
    }
}

// ---------------------------------------------------------------------------
// Kernel 2: persistent fp16 HMMA GEMM + bias + activation -> g_gates (fp16)
// BM=128, BN=128, BK=32, 256 threads, warp tile 32x64, 4-stage cp.async
// grid = 296 (one wave, 2 CTAs/SM), each CTA loops over tiles
// ---------------------------------------------------------------------------
#define STAGES 4
#define STAGE_BYTES 16384     // A: 128*64B = 8192, B: 128*64B = 8192
#define GEMM_SMEM (STAGES * STAGE_BYTES)
#define NIT 24
#define NTILES 3072           // 12 n-blocks x 256 m-blocks
#define GEMM_GRID 296

__device__ __forceinline__ float actv(float v, int ctype) {
    if (ctype == 2) {
        float t = __expf(-2.f * fabsf(v));
        float r = (1.f - t) / (1.f + t);
        return copysignf(r, v);
    }
    return 1.f / (1.f + __expf(-v));
}

__device__ __forceinline__ void gemm_issue(uint32_t smemU, int stage, int kchunk,
                                           int rbase, int n0, int tid) {
    int kc = kchunk * 32;
    int tap = kc >> 8;
    int i0 = kc & 255;
    uint32_t abase = smemU + stage * STAGE_BYTES;
    uint32_t bbase = abase + 8192;
#pragma unroll
    for (int q = 0; q < 2; q++) {
        int idx = tid + q * 256;
        int row = idx >> 2, c16 = idx & 3;
        int chunk = c16 ^ (row & 3) ^ ((row >> 2) & 1);
        cp16(abase + row * 64 + chunk * 16,
             g_xh + (size_t)(rbase + tap + row) * 256 + i0 + c16 * 8);
    }
#pragma unroll
    for (int q = 0; q < 2; q++) {
        int idx = tid + q * 256;
        int row = idx >> 2, c16 = idx & 3;
        int chunk = c16 ^ (row & 3) ^ ((row >> 2) & 1);
        cp16(bbase + row * 64 + chunk * 16,
             g_wh + (size_t)(n0 + row) * 768 + kc + c16 * 8);
    }
}

__global__ __launch_bounds__(256, 2)
void gemm_hmma(const float* __restrict__ bfv, const float* __restrict__ bbv) {
    extern __shared__ char smem[];
    uint32_t smemU = smem_u32(smem);
    const int tid = threadIdx.x;
    const int lane = tid & 31;
    const int w = tid >> 5;
    const int wm = w >> 1;          // 0..3  (32-row slices)
    const int wn = w & 1;           // 0..1  (64-col slices)

    // per-thread ldmatrix read offsets (tile-independent)
    const int lr = lane & 7;
    const int grp = lane >> 3;
    const int arow = wm * 32 + (grp & 1) * 8 + lr;
    const int achk = (grp >> 1) ^ (arow & 3) ^ ((arow >> 2) & 1);
    const uint32_t aoff0 = (uint32_t)(arow * 64 + achk * 16);
    const int brow = wn * 64 + (grp >> 1) * 8 + lr;
    const int bchk = (grp & 1) ^ (brow & 3) ^ ((brow >> 2) & 1);
    const uint32_t boff0 = (uint32_t)(8192 + brow * 64 + bchk * 16);

#pragma unroll 1
    for (int t = blockIdx.x; t < NTILES; t += GEMM_GRID) {
        const int n0 = (t % 12) * 128;
        const int m0 = (t / 12) * 128;
        const int batch = m0 >> 12;
        const int l0 = m0 & 4095;
        const int rbase = batch * LP + l0;

        __syncthreads();   // previous tile's compute fully done before smem reuse

        float acc[2][8][4];
#pragma unroll
        for (int mt = 0; mt < 2; mt++)
#pragma unroll
            for (int nt = 0; nt < 8; nt++)
#pragma unroll
                for (int r = 0; r < 4; r++) acc[mt][nt][r] = 0.f;

        // prologue: fill 3 stages
#pragma unroll
        for (int s = 0; s < STAGES - 1; s++) {
            gemm_issue(smemU, s, s, rbase, n0, tid);
            cp_commit();
        }

#pragma unroll 1
        for (int j = 0; j < NIT; j++) {
            cp_wait<STAGES - 2>();
            __syncthreads();
            if (j + STAGES - 1 < NIT)
                gemm_issue(smemU, (j + STAGES - 1) & (STAGES - 1), j + STAGES - 1, rbase, n0, tid);
            cp_commit();

            uint32_t stbase = smemU + (j & (STAGES - 1)) * STAGE_BYTES;
#pragma unroll
            for (int ks = 0; ks < 2; ks++) {
                uint32_t a[2][4], b[4][4];
#pragma unroll
                for (int mt = 0; mt < 2; mt++)
                    ldsm4(a[mt], (stbase + aoff0 + mt * 1024) ^ (ks * 32));
#pragma unroll
                for (int np = 0; np < 4; np++)
                    ldsm4(b[np], (stbase + boff0 + np * 1024) ^ (ks * 32));
#pragma unroll
                for (int mt = 0; mt < 2; mt++)
#pragma unroll
                    for (int nt = 0; nt < 8; nt++)
                        mma_f16(acc[mt][nt], a[mt], b[nt >> 1][(nt & 1) * 2], b[nt >> 1][(nt & 1) * 2 + 1]);
            }
        }

        // epilogue: bias + activation -> fp16 gates
        const int ctype = (n0 >> 8) % 3;
        const float* bsrc = (n0 < 768) ? bfv : bbv;
        const int cofs = (n0 < 768) ? n0 : (n0 - 768);

#pragma unroll
        for (int mt = 0; mt < 2; mt++) {
            int mrow = m0 + wm * 32 + mt * 16 + (lane >> 2);
            __half* d0 = g_gates + (size_t)mrow * N_TOT + n0;
            __half* d1 = d0 + (size_t)8 * N_TOT;
#pragma unroll
            for (int nt = 0; nt < 8; nt++) {
                int cc = wn * 64 + nt * 8 + (lane & 3) * 2;
                float bb0 = bsrc[cofs + cc];
                float bb1 = bsrc[cofs + cc + 1];
                __half2 v0, v1;
                v0.x = __float2half_rn(actv(acc[mt][nt][0] + bb0, ctype));
                v0.y = __float2half_rn(actv(acc[mt][nt][1] + bb1, ctype));
                v1.x = __float2half_rn(actv(acc[mt][nt][2] + bb0, ctype));
                v1.y = __float2half_rn(actv(acc[mt][nt][3] + bb1, ctype));
                *(__half2*)(d0 + cc) = v0;
                *(__half2*)(d1 + cc) = v1;
            }
        }
    }
}

// ---------------------------------------------------------------------------
// Kernel 3: fused single-pass bidirectional fo-pool scan (R10 structure)
// Pass 1 cached reads; pass 2 streaming (__ldcs) reads + __stcs writes.
// Lookback: wait all predecessors, fold ascending, 4-wide load batching
// (same fold order => bitwise-identical result; batch regs are short-lived).
// ---------------------------------------------------------------------------
__global__ void scan_fused(float* __restrict__ out) {
    const int bid = blockIdx.x;
    const int dir = bid >> 9;
    const int rem = bid & 511;
    const int b = rem >> 6;
    const int pos = rem & 63;
    const int ch = (dir == 0) ? pos : (NCH - 1 - pos);   // chunk index in l-space
    const int d = threadIdx.x;
    const int chain = dir * 8 + b;
    const int slot = chain * NCH + pos;
    const size_t OUT_HL = (size_t)BATCH * LSEQ * 512;

    // ---- pass 1: local aggregate (F = prod f, C = affine offset) ----
    float F = 1.f, C = 0.f;
    {
        const __half* gp;
        int step;
        if (dir == 0) {
            gp = g_gates + (size_t)(b * LSEQ + ch * CHLEN) * N_TOT + d;
            step = N_TOT;
        } else {
            gp = g_gates + (size_t)(b * LSEQ + ch * CHLEN + CHLEN - 1) * N_TOT + 768 + d;
            step = -N_TOT;
        }
#pragma unroll 4
        for (int s = 0; s < CHLEN; s++) {
            float f = __half2float(gp[0]), z = __half2float(gp[512]);
            C = f * C + (1.f - f) * z;
            F *= f;
            gp += step;
        }
    }
    g_aggF[slot * 256 + d] = F;
    g_aggC[slot * 256 + d] = C;
    __syncthreads();
    __threadfence();
    if (d == 0) atomicExch(&g_flag[slot], 1);

    // ---- lookback: wait for all predecessor aggregates, fold ascending ----
    float c = 0.f;
    if (pos > 0) {
        if (d < pos) {
            while (atomicAdd(&g_flag[chain * NCH + d], 0) == 0) { __nanosleep(64); }
        }
        __syncthreads();
        __threadfence();
        const float* aF = g_aggF + (size_t)chain * NCH * 256 + d;
        const float* aC = g_aggC + (size_t)chain * NCH * 256 + d;
        int j = 0;
#pragma unroll 1
        for (; j + 4 <= pos; j += 4) {
            float F0 = aF[(j + 0) * 256], C0 = aC[(j + 0) * 256];
            float F1 = aF[(j + 1) * 256], C1 = aC[(j + 1) * 256];
            float F2 = aF[(j + 2) * 256], C2 = aC[(j + 2) * 256];
            float F3 = aF[(j + 3) * 256], C3 = aC[(j + 3) * 256];
            c = F0 * c + C0;
            c = F1 * c + C1;
            c = F2 * c + C2;
            c = F3 * c + C3;
        }
#pragma unroll 1
        for (; j < pos; j++) {
            c = aF[j * 256] * c + aC[j * 256];
        }
    }

    // ---- pass 2: re-scan chunk (streaming reads), write outputs (__stcs) ----
    if (dir == 0) {
        const __half* gp = g_gates + (size_t)(b * LSEQ + ch * CHLEN) * N_TOT + d;
        float* op = out + (size_t)(b * LSEQ + ch * CHLEN) * 512 + d;
        float h = 0.f;
#pragma unroll 4
        for (int s = 0; s < CHLEN; s++) {
            float f = ldcs_half(gp);
            float o = ldcs_half(gp + 256);
            float z = ldcs_half(gp + 512);
            c = f * c + (1.f - f) * z;
            h = c * o;
            __stcs(op, h);
            gp += N_TOT;
            op += 512;
        }
        if (pos == NCH - 1) {
            __stcs(out + OUT_HL + b * 512 + d, h);
            __stcs(out + OUT_HL + 4096 + b * 512 + d, c);
        }
    } else {
        const __half* gp = g_gates + (size_t)(b * LSEQ + ch * CHLEN + CHLEN - 1) * N_TOT + 768 + d;
        float* op = out + (size_t)(b * LSEQ + ch * CHLEN + CHLEN - 1) * 512 + 256 + d;
        float h_first = 0.f, c_first = 0.f;
#pragma unroll 4
        for (int s = 0; s < CHLEN; s++) {
            float f = ldcs_half(gp);
            float o = ldcs_half(gp + 256);
            float z = ldcs_half(gp + 512);
            c = f * c + (1.f - f) * z;
            float h = c * o;
            __stcs(op, h);
            if (s == 0) { h_first = h; c_first = c; }
            gp -= N_TOT;
            op -= 512;
        }
        if (pos == 0) {    // pos 0 processes l = 4095 first -> rhidden[:, -1]
            __stcs(out + OUT_HL + b * 512 + 256 + d, h_first);
            __stcs(out + OUT_HL + 4096 + b * 512 + 256 + d, c_first);
        }
    }
}

// ---------------------------------------------------------------------------
extern "C" void kernel_launch(void* const* d_in, const int* in_sizes, int n_in,
                              void* d_out, int out_size) {
    const float* x  = (const float*)d_in[0];
    const float* Wf = (const float*)d_in[2];
    const float* bf = (const float*)d_in[3];
    const float* Wb = (const float*)d_in[4];
    const float* bb = (const float*)d_in[5];
    float* out = (float*)d_out;

    cudaFuncSetAttribute(gemm_hmma, cudaFuncAttributeMaxDynamicSharedMemorySize, GEMM_SMEM);

    {
        int totw = N_TOT * K_TOT;                      // largest task
        prep_all<<<(totw + 255) / 256, 256>>>(x, Wf, Wb);
    }
    gemm_hmma<<<GEMM_GRID, 256, GEMM_SMEM>>>(bf, bb);
    scan_fused<<<1024, 256>>>(out);
}